// round 2
// baseline (speedup 1.0000x reference)
#include <cuda_runtime.h>
#include <math.h>

#define BB   64
#define EE   512
#define NN   2048
#define IMGS 64
#define EPSF 1e-8f

// ---- scratch (static device globals; no allocation) ----
__device__ float g_y[BB * IMGS * NN];        // 32 MiB  [b][o][n]
__device__ float g_colpart[BB * 64 * NN];    // 32 MiB  [b][chunk][n]
__device__ float g_colmean[BB * NN];         // 512 KiB
__device__ float g_rowmean[BB * EE];         // 128 KiB
__device__ float g_gpart[8 * BB * IMGS * IMGS]; // 8 MiB [split][b][m*64+n]
__device__ unsigned g_mm[6];                 // min/max per channel (encoded)

// order-preserving float<->uint encoding for atomic min/max
__device__ __forceinline__ unsigned fenc(float f) {
    unsigned u = __float_as_uint(f);
    return (u & 0x80000000u) ? ~u : (u | 0x80000000u);
}
__device__ __forceinline__ float fdec(unsigned e) {
    unsigned u = (e & 0x80000000u) ? (e ^ 0x80000000u) : ~e;
    return __uint_as_float(u);
}

__global__ void k_init() {
    int t = threadIdx.x;
    if (t < 3) g_mm[2 * t] = 0xFFFFFFFFu;      // min slots
    else if (t < 6) g_mm[2 * (t - 3) + 1] = 0u; // max slots
}

// ---------------------------------------------------------------------------
// Pass 1: one CTA per (batch, 8-row chunk). Streams input once.
//  - per-row sum/sumsq -> g_rowmean (temporal raw)
//  - rows chunk*8+3 / +4 centered+normalized -> y[b][chunk][:] (0.5*(xn3+xn4))
//  - partial column sums over the 8 rows -> g_colpart
// ---------------------------------------------------------------------------
__global__ void k_pass1(const float* __restrict__ x) {
    const int chunk = blockIdx.x;   // 0..63  (== output row o of corr resize)
    const int b     = blockIdx.y;   // 0..63
    const int t     = threadIdx.x;  // 0..255
    const int lane  = t & 31, warp = t >> 5;

    __shared__ float4 rowA[512], rowB[512];        // rows 3 and 4 of the chunk
    __shared__ float wsum[8][8], wsq[8][8];        // [warp][row]
    __shared__ float rsum[8], rsq[8];

    float4 cs0 = make_float4(0.f, 0.f, 0.f, 0.f);
    float4 cs1 = make_float4(0.f, 0.f, 0.f, 0.f);
    float ps[8], pq[8];

    const float4* base = (const float4*)x + ((size_t)(b * EE + chunk * 8) * NN) / 4;

    #pragma unroll
    for (int r = 0; r < 8; ++r) {
        const float4* rp = base + (size_t)r * (NN / 4);
        float4 v0 = rp[t];
        float4 v1 = rp[t + 256];

        cs0.x += v0.x; cs0.y += v0.y; cs0.z += v0.z; cs0.w += v0.w;
        cs1.x += v1.x; cs1.y += v1.y; cs1.z += v1.z; cs1.w += v1.w;

        if (r == 3) { rowA[t] = v0; rowA[t + 256] = v1; }
        if (r == 4) { rowB[t] = v0; rowB[t + 256] = v1; }

        ps[r] = v0.x + v0.y + v0.z + v0.w + v1.x + v1.y + v1.z + v1.w;
        pq[r] = v0.x * v0.x + v0.y * v0.y + v0.z * v0.z + v0.w * v0.w +
                v1.x * v1.x + v1.y * v1.y + v1.z * v1.z + v1.w * v1.w;
    }

    // single reduction phase for all 8 rows
    #pragma unroll
    for (int r = 0; r < 8; ++r) {
        float s = ps[r], q = pq[r];
        #pragma unroll
        for (int o = 16; o; o >>= 1) {
            s += __shfl_down_sync(0xFFFFFFFFu, s, o);
            q += __shfl_down_sync(0xFFFFFFFFu, q, o);
        }
        if (lane == 0) { wsum[warp][r] = s; wsq[warp][r] = q; }
    }
    __syncthreads();
    if (t < 8) {  // thread t reduces row t across 8 warps
        float S = 0.f, Q = 0.f;
        #pragma unroll
        for (int w = 0; w < 8; ++w) { S += wsum[w][t]; Q += wsq[w][t]; }
        rsum[t] = S; rsq[t] = Q;
        g_rowmean[b * EE + chunk * 8 + t] = S * (1.0f / NN);
    }
    __syncthreads();

    // stats of the two selected rows
    const float m3 = rsum[3] * (1.0f / NN);
    const float m4 = rsum[4] * (1.0f / NN);
    const float q3 = fmaxf(rsq[3] - (float)NN * m3 * m3, 0.f);
    const float q4 = fmaxf(rsq[4] - (float)NN * m4 * m4, 0.f);
    const float i3 = 0.5f / (sqrtf(q3) + EPSF);  // fold the 0.5 resize weight in
    const float i4 = 0.5f / (sqrtf(q4) + EPSF);

    float4* yb = (float4*)g_y + ((size_t)(b * IMGS + chunk) * NN) / 4;
    float4 a0 = rowA[t], a1 = rowA[t + 256];
    float4 b0 = rowB[t], b1 = rowB[t + 256];
    float4 y0, y1;
    y0.x = (a0.x - m3) * i3 + (b0.x - m4) * i4;
    y0.y = (a0.y - m3) * i3 + (b0.y - m4) * i4;
    y0.z = (a0.z - m3) * i3 + (b0.z - m4) * i4;
    y0.w = (a0.w - m3) * i3 + (b0.w - m4) * i4;
    y1.x = (a1.x - m3) * i3 + (b1.x - m4) * i4;
    y1.y = (a1.y - m3) * i3 + (b1.y - m4) * i4;
    y1.z = (a1.z - m3) * i3 + (b1.z - m4) * i4;
    y1.w = (a1.w - m3) * i3 + (b1.w - m4) * i4;
    yb[t] = y0; yb[t + 256] = y1;

    float4* cp = (float4*)g_colpart + ((size_t)(b * 64 + chunk) * NN) / 4;
    cp[t] = cs0; cp[t + 256] = cs1;
}

// deterministic reduction of column partials -> column mean (mean over E)
__global__ void k_colreduce() {
    int idx = blockIdx.x * blockDim.x + threadIdx.x;  // < B*N
    int b = idx >> 11, n = idx & (NN - 1);
    float s = 0.f;
    #pragma unroll
    for (int c = 0; c < 64; ++c)
        s += g_colpart[((size_t)(b * 64 + c)) * NN + n];
    g_colmean[idx] = s * (1.0f / EE);
}

// bilinear taps matching F.interpolate(align_corners=False) incl. clamping
__device__ __forceinline__ void taps(int o, int in, int& p0, int& p1, float& w) {
    double s = ((double)o + 0.5) * ((double)in / (double)IMGS) - 0.5;
    if (s < 0.0) s = 0.0;
    if (s > (double)(in - 1)) s = (double)(in - 1);
    p0 = (int)floor(s);
    w  = (float)(s - (double)p0);
    p1 = min(p0 + 1, in - 1);
}

__device__ __forceinline__ float gridval(const float* __restrict__ v, int L, int gs,
                                         int r, int c) {
    int p = r * gs + c;
    return (p < L) ? v[p] : 0.f;
}

__device__ __forceinline__ void block_minmax_atomic(float mn, float mx, int ch) {
    #pragma unroll
    for (int o = 16; o; o >>= 1) {
        mn = fminf(mn, __shfl_down_sync(0xFFFFFFFFu, mn, o));
        mx = fmaxf(mx, __shfl_down_sync(0xFFFFFFFFu, mx, o));
    }
    __shared__ float smn[8], smx[8];
    int lane = threadIdx.x & 31, warp = threadIdx.x >> 5;
    if (lane == 0) { smn[warp] = mn; smx[warp] = mx; }
    __syncthreads();
    if (threadIdx.x == 0) {
        float a = smn[0], c = smx[0];
        #pragma unroll
        for (int w = 1; w < 8; ++w) { a = fminf(a, smn[w]); c = fmaxf(c, smx[w]); }
        atomicMin(&g_mm[2 * ch], fenc(a));
        atomicMax(&g_mm[2 * ch + 1], fenc(c));
    }
}

// temporal (sel=0: rowmean, gs=23) / spatial (sel=1: colmean, gs=46) views
__global__ void k_view(float* __restrict__ out, int sel) {
    int idx = blockIdx.x * blockDim.x + threadIdx.x;  // < B*4096
    int b = idx >> 12, ij = idx & 4095;
    int i = ij >> 6, j = ij & 63;

    const float* v; int L, gs, ch;
    if (sel == 0) { v = g_rowmean + (size_t)b * EE; L = EE; gs = 23; ch = 0; }
    else          { v = g_colmean + (size_t)b * NN; L = NN; gs = 46; ch = 1; }

    int i0, i1, j0, j1; float wi, wj;
    taps(i, gs, i0, i1, wi);
    taps(j, gs, j0, j1, wj);

    float v00 = gridval(v, L, gs, i0, j0), v01 = gridval(v, L, gs, i0, j1);
    float v10 = gridval(v, L, gs, i1, j0), v11 = gridval(v, L, gs, i1, j1);
    float val = (1.f - wi) * ((1.f - wj) * v00 + wj * v01) +
                wi * ((1.f - wj) * v10 + wj * v11);

    out[((size_t)(b * 3 + ch)) * 4096 + ij] = val;
    block_minmax_atomic(val, val, ch);
}

// corr view: resized corr = y @ y^T, 64x64xK per batch, split-K=8 over K=2048
__global__ void k_gemm() {
    const int b = blockIdx.x;   // batch
    const int s = blockIdx.y;   // k-split 0..7
    const int t = threadIdx.x;  // 0..255

    __shared__ float T[64 * 65];  // k-major tile: T[k*65 + m]

    const int lr = t >> 2;          // m row loaded by this thread
    const int lc = (t & 3) * 16;    // k offset within 64-tile
    const int ty = t >> 4, tx = t & 15;

    const float* Yb = g_y + (size_t)b * IMGS * NN;
    float acc[4][4];
    #pragma unroll
    for (int i = 0; i < 4; ++i)
        #pragma unroll
        for (int j = 0; j < 4; ++j) acc[i][j] = 0.f;

    for (int kt = 0; kt < 4; ++kt) {
        const int kb = s * 256 + kt * 64;
        const float4* src = (const float4*)(Yb + (size_t)lr * NN + kb + lc);
        #pragma unroll
        for (int u = 0; u < 4; ++u) {
            float4 q = src[u];
            int kc = lc + u * 4;
            T[(kc + 0) * 65 + lr] = q.x;
            T[(kc + 1) * 65 + lr] = q.y;
            T[(kc + 2) * 65 + lr] = q.z;
            T[(kc + 3) * 65 + lr] = q.w;
        }
        __syncthreads();

        #pragma unroll 4
        for (int k = 0; k < 64; ++k) {
            const float* Tk = &T[k * 65];
            float a0 = Tk[ty * 4 + 0], a1 = Tk[ty * 4 + 1];
            float a2 = Tk[ty * 4 + 2], a3 = Tk[ty * 4 + 3];
            float c0 = Tk[tx * 4 + 0], c1 = Tk[tx * 4 + 1];
            float c2 = Tk[tx * 4 + 2], c3 = Tk[tx * 4 + 3];
            acc[0][0] += a0 * c0; acc[0][1] += a0 * c1; acc[0][2] += a0 * c2; acc[0][3] += a0 * c3;
            acc[1][0] += a1 * c0; acc[1][1] += a1 * c1; acc[1][2] += a1 * c2; acc[1][3] += a1 * c3;
            acc[2][0] += a2 * c0; acc[2][1] += a2 * c1; acc[2][2] += a2 * c2; acc[2][3] += a2 * c3;
            acc[3][0] += a3 * c0; acc[3][1] += a3 * c1; acc[3][2] += a3 * c2; acc[3][3] += a3 * c3;
        }
        __syncthreads();
    }

    float* gp = g_gpart + (size_t)s * (BB * 4096) + (size_t)b * 4096;
    #pragma unroll
    for (int i = 0; i < 4; ++i)
        #pragma unroll
        for (int j = 0; j < 4; ++j)
            gp[(ty * 4 + i) * 64 + tx * 4 + j] = acc[i][j];
}

// sum split-K partials -> channel 2 raw + minmax
__global__ void k_creduce(float* __restrict__ out) {
    int idx = blockIdx.x * blockDim.x + threadIdx.x;  // < B*4096
    int b = idx >> 12, mn = idx & 4095;
    float v = 0.f;
    #pragma unroll
    for (int s = 0; s < 8; ++s) v += g_gpart[(size_t)s * (BB * 4096) + idx];
    out[((size_t)(b * 3 + 2)) * 4096 + mn] = v;
    block_minmax_atomic(v, v, 2);
}

// global per-channel min-max normalization, in place
__global__ void k_norm(float* __restrict__ out) {
    int idx = blockIdx.x * blockDim.x + threadIdx.x;  // < B*3*4096
    int ch = (idx >> 12) % 3;
    float lo = fdec(g_mm[2 * ch]);
    float hi = fdec(g_mm[2 * ch + 1]);
    float d = hi - lo;
    float x = out[idx];
    out[idx] = (d < EPSF) ? 0.f : (x - lo) / (d + EPSF);
}

extern "C" void kernel_launch(void* const* d_in, const int* in_sizes, int n_in,
                              void* d_out, int out_size) {
    const float* x = (const float*)d_in[0];
    float* out = (float*)d_out;

    k_init<<<1, 32>>>();
    k_pass1<<<dim3(64, 64), 256>>>(x);
    k_colreduce<<<(BB * NN) / 256, 256>>>();
    k_view<<<(BB * 4096) / 256, 256>>>(out, 0);
    k_view<<<(BB * 4096) / 256, 256>>>(out, 1);
    k_gemm<<<dim3(64, 8), 256>>>();
    k_creduce<<<(BB * 4096) / 256, 256>>>(out);
    k_norm<<<(BB * 3 * 4096) / 256, 256>>>(out);
}

// round 3
// speedup vs baseline: 1.2691x; 1.2691x over previous
#include <cuda_runtime.h>
#include <math.h>

#define BB   64
#define EE   512
#define NN   2048
#define IMGS 64
#define EPSF 1e-8f

// ---- scratch (static device globals; no allocation) ----
__device__ float g_y[BB * IMGS * NN];           // 32 MiB  [b][o][n]
__device__ float g_colpart[BB * 32 * NN];       // 16 MiB  [b][chunk][n]
__device__ float g_rowmean[BB * EE];            // 128 KiB
__device__ float g_gpart[8 * BB * IMGS * IMGS]; // 8 MiB [split][b][m*64+n]
__device__ unsigned g_mm[6];                    // min/max per channel (encoded)

// order-preserving float<->uint encoding for atomic min/max
__device__ __forceinline__ unsigned fenc(float f) {
    unsigned u = __float_as_uint(f);
    return (u & 0x80000000u) ? ~u : (u | 0x80000000u);
}
__device__ __forceinline__ float fdec(unsigned e) {
    unsigned u = (e & 0x80000000u) ? (e ^ 0x80000000u) : ~e;
    return __uint_as_float(u);
}

// packed fp32x2 helpers (FFMA2 path — 2x fp32 throughput vs 3-reg FFMA)
__device__ __forceinline__ unsigned long long pack2(float x, float y) {
    unsigned long long r;
    asm("mov.b64 %0, {%1, %2};" : "=l"(r) : "f"(x), "f"(y));
    return r;
}
__device__ __forceinline__ void fma2(unsigned long long& d,
                                     unsigned long long a, unsigned long long b) {
    asm("fma.rn.f32x2 %0, %1, %2, %0;" : "+l"(d) : "l"(a), "l"(b));
}
__device__ __forceinline__ float sum2(unsigned long long p) {
    float lo, hi;
    asm("mov.b64 {%0, %1}, %2;" : "=f"(lo), "=f"(hi) : "l"(p));
    return lo + hi;
}

// ---------------------------------------------------------------------------
// Pass 1: one CTA per (batch, 16-row chunk). Streams input once.
//  - per-row mean -> g_rowmean (temporal raw)
//  - rows chunk*16+{3,4} -> y row 2*chunk ; +{11,12} -> y row 2*chunk+1
//    (centered, normalized, 0.5 resize weight folded in)
//  - partial column sums over the 16 rows -> g_colpart
// ---------------------------------------------------------------------------
__global__ void __launch_bounds__(256) k_pass1(const float* __restrict__ x) {
    const int chunk = blockIdx.x;   // 0..31
    const int b     = blockIdx.y;   // 0..63
    const int t     = threadIdx.x;  // 0..255
    const int lane  = t & 31, warp = t >> 5;

    if (chunk == 0 && b == 0) {     // fold g_mm init in (consumers run later)
        if (t < 3) g_mm[2 * t] = 0xFFFFFFFFu;
        else if (t < 6) g_mm[2 * (t - 3) + 1] = 0u;
    }

    __shared__ float4 rows[4][512];          // rows 3,4,11,12 of the chunk
    __shared__ float wsum[8][16], wsq[8][16];
    __shared__ float rsum[16], rsq[16];

    float4 cs0 = make_float4(0.f, 0.f, 0.f, 0.f);
    float4 cs1 = make_float4(0.f, 0.f, 0.f, 0.f);
    float ps[16], pq[16];

    const float4* base = (const float4*)x + ((size_t)(b * EE + chunk * 16) * NN) / 4;

    #pragma unroll
    for (int r = 0; r < 16; ++r) {
        const float4* rp = base + (size_t)r * (NN / 4);
        float4 v0 = rp[t];
        float4 v1 = rp[t + 256];

        cs0.x += v0.x; cs0.y += v0.y; cs0.z += v0.z; cs0.w += v0.w;
        cs1.x += v1.x; cs1.y += v1.y; cs1.z += v1.z; cs1.w += v1.w;

        if (r == 3)  { rows[0][t] = v0; rows[0][t + 256] = v1; }
        if (r == 4)  { rows[1][t] = v0; rows[1][t + 256] = v1; }
        if (r == 11) { rows[2][t] = v0; rows[2][t + 256] = v1; }
        if (r == 12) { rows[3][t] = v0; rows[3][t + 256] = v1; }

        ps[r] = v0.x + v0.y + v0.z + v0.w + v1.x + v1.y + v1.z + v1.w;
        pq[r] = v0.x * v0.x + v0.y * v0.y + v0.z * v0.z + v0.w * v0.w +
                v1.x * v1.x + v1.y * v1.y + v1.z * v1.z + v1.w * v1.w;
    }

    #pragma unroll
    for (int r = 0; r < 16; ++r) {
        float s = ps[r], q = pq[r];
        #pragma unroll
        for (int o = 16; o; o >>= 1) {
            s += __shfl_down_sync(0xFFFFFFFFu, s, o);
            q += __shfl_down_sync(0xFFFFFFFFu, q, o);
        }
        if (lane == 0) { wsum[warp][r] = s; wsq[warp][r] = q; }
    }
    __syncthreads();
    if (t < 16) {
        float S = 0.f, Q = 0.f;
        #pragma unroll
        for (int w = 0; w < 8; ++w) { S += wsum[w][t]; Q += wsq[w][t]; }
        rsum[t] = S; rsq[t] = Q;
        g_rowmean[b * EE + chunk * 16 + t] = S * (1.0f / NN);
    }
    __syncthreads();

    // stats of the four selected rows; fold 0.5 resize weight into inv-norm
    float m[4], inv[4];
    const int sel[4] = {3, 4, 11, 12};
    #pragma unroll
    for (int p = 0; p < 4; ++p) {
        m[p] = rsum[sel[p]] * (1.0f / NN);
        float q = fmaxf(rsq[sel[p]] - (float)NN * m[p] * m[p], 0.f);
        inv[p] = 0.5f / (sqrtf(q) + EPSF);
    }

    #pragma unroll
    for (int half = 0; half < 2; ++half) {  // half 0 -> y row 2c, 1 -> 2c+1
        float4* yb = (float4*)g_y +
                     ((size_t)(b * IMGS + chunk * 2 + half) * NN) / 4;
        const float mA = m[2 * half], mB = m[2 * half + 1];
        const float iA = inv[2 * half], iB = inv[2 * half + 1];
        #pragma unroll
        for (int u = 0; u < 2; ++u) {
            float4 a = rows[2 * half][t + 256 * u];
            float4 c = rows[2 * half + 1][t + 256 * u];
            float4 y;
            y.x = (a.x - mA) * iA + (c.x - mB) * iB;
            y.y = (a.y - mA) * iA + (c.y - mB) * iB;
            y.z = (a.z - mA) * iA + (c.z - mB) * iB;
            y.w = (a.w - mA) * iA + (c.w - mB) * iB;
            yb[t + 256 * u] = y;
        }
    }

    float4* cp = (float4*)g_colpart + ((size_t)(b * 32 + chunk) * NN) / 4;
    cp[t] = cs0; cp[t + 256] = cs1;
}

// block-wide minmax -> global atomics (entry sync so it can be called twice)
__device__ __forceinline__ void block_minmax_atomic(float mn, float mx, int ch) {
    __shared__ float smn[8], smx[8];
    __syncthreads();
    #pragma unroll
    for (int o = 16; o; o >>= 1) {
        mn = fminf(mn, __shfl_down_sync(0xFFFFFFFFu, mn, o));
        mx = fmaxf(mx, __shfl_down_sync(0xFFFFFFFFu, mx, o));
    }
    int lane = threadIdx.x & 31, warp = threadIdx.x >> 5;
    if (lane == 0) { smn[warp] = mn; smx[warp] = mx; }
    __syncthreads();
    if (threadIdx.x == 0) {
        float a = smn[0], c = smx[0];
        #pragma unroll
        for (int w = 1; w < 8; ++w) { a = fminf(a, smn[w]); c = fmaxf(c, smx[w]); }
        atomicMin(&g_mm[2 * ch], fenc(a));
        atomicMax(&g_mm[2 * ch + 1], fenc(c));
    }
}

// ---------------------------------------------------------------------------
// Views: one CTA per batch. colmean reduction + both bilinear views in smem.
// Tap math is exact in fp32 (scale denominators are powers of two).
// ---------------------------------------------------------------------------
__global__ void __launch_bounds__(256) k_views(float* __restrict__ out) {
    const int b = blockIdx.x;
    const int t = threadIdx.x;

    __shared__ __align__(16) float srow[EE];
    __shared__ __align__(16) float scol[NN];
    __shared__ int   i0t[2][64], i1t[2][64];
    __shared__ float wt[2][64];

    // row means
    srow[t]       = g_rowmean[b * EE + t];
    srow[t + 256] = g_rowmean[b * EE + t + 256];

    // column means: reduce 32 partials
    {
        float4 s0 = make_float4(0.f, 0.f, 0.f, 0.f);
        float4 s1 = make_float4(0.f, 0.f, 0.f, 0.f);
        const float4* cp = (const float4*)g_colpart + (size_t)b * 32 * (NN / 4);
        #pragma unroll 8
        for (int c = 0; c < 32; ++c) {
            float4 v0 = cp[c * (NN / 4) + t];
            float4 v1 = cp[c * (NN / 4) + t + 256];
            s0.x += v0.x; s0.y += v0.y; s0.z += v0.z; s0.w += v0.w;
            s1.x += v1.x; s1.y += v1.y; s1.z += v1.z; s1.w += v1.w;
        }
        const float k = 1.0f / EE;
        s0.x *= k; s0.y *= k; s0.z *= k; s0.w *= k;
        s1.x *= k; s1.y *= k; s1.z *= k; s1.w *= k;
        ((float4*)scol)[t] = s0;
        ((float4*)scol)[t + 256] = s1;
    }

    // tap tables: sel 0 -> gs=23, sel 1 -> gs=46
    if (t < 128) {
        int sel = t >> 6, o = t & 63;
        int gs = sel ? 46 : 23;
        float src = ((float)o + 0.5f) * ((float)gs / (float)IMGS) - 0.5f;
        src = fminf(fmaxf(src, 0.f), (float)(gs - 1));
        int p0 = (int)floorf(src);
        i0t[sel][o] = p0;
        i1t[sel][o] = min(p0 + 1, gs - 1);
        wt[sel][o]  = src - (float)p0;
    }
    __syncthreads();

    #pragma unroll
    for (int sel = 0; sel < 2; ++sel) {
        const float* v = sel ? scol : srow;
        const int L = sel ? NN : EE;
        const int gs = sel ? 46 : 23;
        float mn = 3.0e38f, mx = -3.0e38f;
        #pragma unroll
        for (int u = 0; u < 16; ++u) {
            int ij = t + 256 * u;
            int i = ij >> 6, j = ij & 63;
            int i0 = i0t[sel][i], i1 = i1t[sel][i];
            int j0 = i0t[sel][j], j1 = i1t[sel][j];
            float wi = wt[sel][i], wj = wt[sel][j];
            int p00 = i0 * gs + j0, p01 = i0 * gs + j1;
            int p10 = i1 * gs + j0, p11 = i1 * gs + j1;
            float v00 = (p00 < L) ? v[p00] : 0.f;
            float v01 = (p01 < L) ? v[p01] : 0.f;
            float v10 = (p10 < L) ? v[p10] : 0.f;
            float v11 = (p11 < L) ? v[p11] : 0.f;
            float val = (1.f - wi) * ((1.f - wj) * v00 + wj * v01) +
                        wi * ((1.f - wj) * v10 + wj * v11);
            out[((size_t)(b * 3 + sel)) * 4096 + ij] = val;
            mn = fminf(mn, val); mx = fmaxf(mx, val);
        }
        block_minmax_atomic(mn, mx, sel);
    }
}

// ---------------------------------------------------------------------------
// corr view: resized corr = y @ y^T per batch, split-K=8, packed f32x2 FMA
// ---------------------------------------------------------------------------
__global__ void __launch_bounds__(256) k_gemm() {
    const int b = blockIdx.x;   // batch
    const int s = blockIdx.y;   // k-split 0..7
    const int t = threadIdx.x;  // 0..255

    __shared__ unsigned long long T2[32 * 65];  // [k2][m] packed (k,k+1) pairs

    const int lr = t >> 2;           // m row loaded by this thread
    const int lc = (t & 3) * 16;     // k offset within 64-tile
    const int ty = t >> 4, tx = t & 15;

    const float* Yb = g_y + (size_t)b * IMGS * NN;
    unsigned long long acc[4][4];
    #pragma unroll
    for (int i = 0; i < 4; ++i)
        #pragma unroll
        for (int j = 0; j < 4; ++j) acc[i][j] = 0ull;

    for (int kt = 0; kt < 4; ++kt) {
        const int kb = s * 256 + kt * 64;
        const float4* src = (const float4*)(Yb + (size_t)lr * NN + kb + lc);
        #pragma unroll
        for (int u = 0; u < 4; ++u) {
            float4 q = src[u];
            int k2 = (lc >> 1) + 2 * u;
            T2[k2 * 65 + lr]       = pack2(q.x, q.y);
            T2[(k2 + 1) * 65 + lr] = pack2(q.z, q.w);
        }
        __syncthreads();

        #pragma unroll 4
        for (int k2 = 0; k2 < 32; ++k2) {
            const unsigned long long* Tk = &T2[k2 * 65];
            unsigned long long a0 = Tk[ty],      a1 = Tk[ty + 16];
            unsigned long long a2 = Tk[ty + 32], a3 = Tk[ty + 48];
            unsigned long long c0 = Tk[tx],      c1 = Tk[tx + 16];
            unsigned long long c2 = Tk[tx + 32], c3 = Tk[tx + 48];
            fma2(acc[0][0], a0, c0); fma2(acc[0][1], a0, c1);
            fma2(acc[0][2], a0, c2); fma2(acc[0][3], a0, c3);
            fma2(acc[1][0], a1, c0); fma2(acc[1][1], a1, c1);
            fma2(acc[1][2], a1, c2); fma2(acc[1][3], a1, c3);
            fma2(acc[2][0], a2, c0); fma2(acc[2][1], a2, c1);
            fma2(acc[2][2], a2, c2); fma2(acc[2][3], a2, c3);
            fma2(acc[3][0], a3, c0); fma2(acc[3][1], a3, c1);
            fma2(acc[3][2], a3, c2); fma2(acc[3][3], a3, c3);
        }
        __syncthreads();
    }

    float* gp = g_gpart + (size_t)s * (BB * 4096) + (size_t)b * 4096;
    #pragma unroll
    for (int i = 0; i < 4; ++i)
        #pragma unroll
        for (int j = 0; j < 4; ++j)
            gp[(ty + 16 * i) * 64 + tx + 16 * j] = sum2(acc[i][j]);
}

// sum split-K partials -> channel 2 raw + minmax
__global__ void __launch_bounds__(256) k_creduce(float* __restrict__ out) {
    int idx = blockIdx.x * blockDim.x + threadIdx.x;  // < B*4096
    int b = idx >> 12, mn = idx & 4095;
    float v = 0.f;
    #pragma unroll
    for (int s = 0; s < 8; ++s) v += g_gpart[(size_t)s * (BB * 4096) + idx];
    out[((size_t)(b * 3 + 2)) * 4096 + mn] = v;
    block_minmax_atomic(v, v, 2);
}

// global per-channel min-max normalization, in place
__global__ void __launch_bounds__(256) k_norm(float* __restrict__ out) {
    int idx = blockIdx.x * blockDim.x + threadIdx.x;  // < B*3*4096
    int ch = (idx >> 12) % 3;
    float lo = fdec(g_mm[2 * ch]);
    float hi = fdec(g_mm[2 * ch + 1]);
    float d = hi - lo;
    float x = out[idx];
    out[idx] = (d < EPSF) ? 0.f : (x - lo) / (d + EPSF);
}

extern "C" void kernel_launch(void* const* d_in, const int* in_sizes, int n_in,
                              void* d_out, int out_size) {
    const float* x = (const float*)d_in[0];
    float* out = (float*)d_out;

    k_pass1<<<dim3(32, 64), 256>>>(x);
    k_gemm<<<dim3(64, 8), 256>>>();
    k_views<<<64, 256>>>(out);
    k_creduce<<<(BB * 4096) / 256, 256>>>(out);
    k_norm<<<(BB * 3 * 4096) / 256, 256>>>(out);
}

// round 4
// speedup vs baseline: 1.4436x; 1.1375x over previous
#include <cuda_runtime.h>
#include <cuda_bf16.h>
#include <math.h>

#define BB   64
#define EE   512
#define NN   2048
#define IMGS 64
#define EPSF 1e-8f

// ---- scratch (static device globals; no allocation) ----
__device__ __nv_bfloat16 g_y[BB * IMGS * NN];   // 16 MiB  [b][o][n]
__device__ float g_colpart[BB * 32 * NN];       // 16 MiB  [b][chunk][n]
__device__ float g_rowmean[BB * EE];            // 128 KiB
__device__ unsigned g_mm[6];                    // min/max per channel (encoded)

// order-preserving float<->uint encoding for atomic min/max
__device__ __forceinline__ unsigned fenc(float f) {
    unsigned u = __float_as_uint(f);
    return (u & 0x80000000u) ? ~u : (u | 0x80000000u);
}
__device__ __forceinline__ float fdec(unsigned e) {
    unsigned u = (e & 0x80000000u) ? (e ^ 0x80000000u) : ~e;
    return __uint_as_float(u);
}

__device__ __forceinline__ unsigned smem_u32(const void* p) {
    unsigned a;
    asm("{ .reg .u64 t; cvta.to.shared.u64 t, %1; cvt.u32.u64 %0, t; }"
        : "=r"(a) : "l"(p));
    return a;
}

// ---------------------------------------------------------------------------
// Pass 1: one CTA per (batch, 16-row chunk). Streams input once.
//  - per-row mean -> g_rowmean (temporal raw)
//  - rows chunk*16+{3,4} -> y row 2*chunk ; +{11,12} -> y row 2*chunk+1
//    (centered, normalized, 0.5 resize weight folded; stored bf16)
//  - partial column sums over the 16 rows -> g_colpart
// ---------------------------------------------------------------------------
__global__ void __launch_bounds__(256) k_pass1(const float* __restrict__ x) {
    const int chunk = blockIdx.x;   // 0..31
    const int b     = blockIdx.y;   // 0..63
    const int t     = threadIdx.x;  // 0..255
    const int lane  = t & 31, warp = t >> 5;

    if (chunk == 0 && b == 0) {     // fold g_mm init in (consumers run later)
        if (t < 3) g_mm[2 * t] = 0xFFFFFFFFu;
        else if (t < 6) g_mm[2 * (t - 3) + 1] = 0u;
    }

    __shared__ float4 rows[4][512];          // rows 3,4,11,12 of the chunk
    __shared__ float wsum[8][16], wsq[8][16];
    __shared__ float rsum[16], rsq[16];

    float4 cs0 = make_float4(0.f, 0.f, 0.f, 0.f);
    float4 cs1 = make_float4(0.f, 0.f, 0.f, 0.f);
    float ps[16], pq[16];

    const float4* base = (const float4*)x + ((size_t)(b * EE + chunk * 16) * NN) / 4;

    #pragma unroll
    for (int r = 0; r < 16; ++r) {
        const float4* rp = base + (size_t)r * (NN / 4);
        float4 v0 = rp[t];
        float4 v1 = rp[t + 256];

        cs0.x += v0.x; cs0.y += v0.y; cs0.z += v0.z; cs0.w += v0.w;
        cs1.x += v1.x; cs1.y += v1.y; cs1.z += v1.z; cs1.w += v1.w;

        if (r == 3)  { rows[0][t] = v0; rows[0][t + 256] = v1; }
        if (r == 4)  { rows[1][t] = v0; rows[1][t + 256] = v1; }
        if (r == 11) { rows[2][t] = v0; rows[2][t + 256] = v1; }
        if (r == 12) { rows[3][t] = v0; rows[3][t + 256] = v1; }

        ps[r] = v0.x + v0.y + v0.z + v0.w + v1.x + v1.y + v1.z + v1.w;
        pq[r] = v0.x * v0.x + v0.y * v0.y + v0.z * v0.z + v0.w * v0.w +
                v1.x * v1.x + v1.y * v1.y + v1.z * v1.z + v1.w * v1.w;
    }

    #pragma unroll
    for (int r = 0; r < 16; ++r) {
        float s = ps[r], q = pq[r];
        #pragma unroll
        for (int o = 16; o; o >>= 1) {
            s += __shfl_down_sync(0xFFFFFFFFu, s, o);
            q += __shfl_down_sync(0xFFFFFFFFu, q, o);
        }
        if (lane == 0) { wsum[warp][r] = s; wsq[warp][r] = q; }
    }
    __syncthreads();
    if (t < 16) {
        float S = 0.f, Q = 0.f;
        #pragma unroll
        for (int w = 0; w < 8; ++w) { S += wsum[w][t]; Q += wsq[w][t]; }
        rsum[t] = S; rsq[t] = Q;
        g_rowmean[b * EE + chunk * 16 + t] = S * (1.0f / NN);
    }
    __syncthreads();

    // stats of the four selected rows; fold 0.5 resize weight into inv-norm
    float m[4], inv[4];
    const int sel[4] = {3, 4, 11, 12};
    #pragma unroll
    for (int p = 0; p < 4; ++p) {
        m[p] = rsum[sel[p]] * (1.0f / NN);
        float q = fmaxf(rsq[sel[p]] - (float)NN * m[p] * m[p], 0.f);
        inv[p] = 0.5f / (sqrtf(q) + EPSF);
    }

    #pragma unroll
    for (int half = 0; half < 2; ++half) {  // half 0 -> y row 2c, 1 -> 2c+1
        uint2* yb = (uint2*)(g_y + (size_t)(b * IMGS + chunk * 2 + half) * NN);
        const float mA = m[2 * half], mB = m[2 * half + 1];
        const float iA = inv[2 * half], iB = inv[2 * half + 1];
        #pragma unroll
        for (int u = 0; u < 2; ++u) {
            float4 a = rows[2 * half][t + 256 * u];
            float4 c = rows[2 * half + 1][t + 256 * u];
            float4 y;
            y.x = (a.x - mA) * iA + (c.x - mB) * iB;
            y.y = (a.y - mA) * iA + (c.y - mB) * iB;
            y.z = (a.z - mA) * iA + (c.z - mB) * iB;
            y.w = (a.w - mA) * iA + (c.w - mB) * iB;
            __nv_bfloat162 h0 = __floats2bfloat162_rn(y.x, y.y);
            __nv_bfloat162 h1 = __floats2bfloat162_rn(y.z, y.w);
            uint2 pk;
            pk.x = *(unsigned*)&h0;
            pk.y = *(unsigned*)&h1;
            yb[t + 256 * u] = pk;
        }
    }

    float4* cp = (float4*)g_colpart + ((size_t)(b * 32 + chunk) * NN) / 4;
    cp[t] = cs0; cp[t + 256] = cs1;
}

// block-wide minmax -> global atomics (entry sync so it can be called twice)
__device__ __forceinline__ void block_minmax_atomic(float mn, float mx, int ch) {
    __shared__ float smn[8], smx[8];
    __syncthreads();
    #pragma unroll
    for (int o = 16; o; o >>= 1) {
        mn = fminf(mn, __shfl_down_sync(0xFFFFFFFFu, mn, o));
        mx = fmaxf(mx, __shfl_down_sync(0xFFFFFFFFu, mx, o));
    }
    int lane = threadIdx.x & 31, warp = threadIdx.x >> 5;
    if (lane == 0) { smn[warp] = mn; smx[warp] = mx; }
    __syncthreads();
    if (threadIdx.x == 0) {
        float a = smn[0], c = smx[0];
        #pragma unroll
        for (int w = 1; w < 8; ++w) { a = fminf(a, smn[w]); c = fmaxf(c, smx[w]); }
        atomicMin(&g_mm[2 * ch], fenc(a));
        atomicMax(&g_mm[2 * ch + 1], fenc(c));
    }
}

// ---------------------------------------------------------------------------
// corr view: resized corr = y @ y^T per batch via bf16 mma.sync (fp32 accum).
// One CTA per batch, 8 warps (4x2 over the 64x64 output), K=2048 in one pass.
// Writes channel 2 directly + minmax. No split-K scratch.
// ---------------------------------------------------------------------------
__global__ void __launch_bounds__(256) k_gemm(float* __restrict__ out) {
    const int b    = blockIdx.x;
    const int t    = threadIdx.x;
    const int warp = t >> 5, lane = t & 31;
    const int wm   = warp >> 1;        // 0..3  -> rows 16*wm
    const int wn   = warp & 1;         // 0..1  -> cols 32*wn

    __shared__ __align__(16) char sm[2][64 * 128];  // double-buffered 64x64 bf16

    const __nv_bfloat16* Yb = g_y + (size_t)b * IMGS * NN;

    // loader: thread t -> row t>>2, two 16B chunks (t&3)*2 + {0,1}
    const int lrow = t >> 2;
    const int lch0 = (t & 3) * 2;

    // ldmatrix lane addressing (swizzle xor = (row&7)<<4)
    const int arow = wm * 16 + (lane & 15);
    const int brow0 = wn * 32 + (lane & 15);       // B pair 0 (n 0..15)
    const int brow1 = wn * 32 + 16 + (lane & 15);  // B pair 1 (n 16..31)
    const int chalf = (lane >> 4) * 16;            // 0 or 16 bytes (k half)
    const unsigned smb = smem_u32(sm);

    float acc[4][4];
    #pragma unroll
    for (int j = 0; j < 4; ++j)
        #pragma unroll
        for (int r = 0; r < 4; ++r) acc[j][r] = 0.f;

    // preload tile 0
    {
        const uint4* src = (const uint4*)(Yb + (size_t)lrow * NN);
        #pragma unroll
        for (int u = 0; u < 2; ++u) {
            int ch = lch0 + u;
            uint4 v = src[ch];
            int off = lrow * 128 + ch * 16;
            int sw = off ^ ((off >> 3) & 0x70);
            *(uint4*)(sm[0] + sw) = v;
        }
    }
    __syncthreads();

    for (int kt = 0; kt < 32; ++kt) {
        const int buf = kt & 1;
        if (kt + 1 < 32) {
            const uint4* src = (const uint4*)(Yb + (size_t)lrow * NN + (kt + 1) * 64);
            #pragma unroll
            for (int u = 0; u < 2; ++u) {
                int ch = lch0 + u;
                uint4 v = src[ch];
                int off = lrow * 128 + ch * 16;
                int sw = off ^ ((off >> 3) & 0x70);
                *(uint4*)(sm[buf ^ 1] + sw) = v;
            }
        }

        const unsigned base = smb + buf * (64 * 128);
        #pragma unroll
        for (int ks = 0; ks < 4; ++ks) {
            const int kb = ks * 32;  // byte offset of this k-step (16 bf16)
            unsigned a0, a1, a2, a3;
            {
                int off = arow * 128 + kb + chalf;
                unsigned ad = base + (off ^ ((arow & 7) << 4));
                asm volatile("ldmatrix.sync.aligned.m8n8.x4.shared.b16 "
                             "{%0,%1,%2,%3}, [%4];"
                             : "=r"(a0), "=r"(a1), "=r"(a2), "=r"(a3) : "r"(ad));
            }
            unsigned q0, q1, q2, q3, p0, p1, p2, p3;
            {
                int off = brow0 * 128 + kb + chalf;
                unsigned ad = base + (off ^ ((brow0 & 7) << 4));
                asm volatile("ldmatrix.sync.aligned.m8n8.x4.shared.b16 "
                             "{%0,%1,%2,%3}, [%4];"
                             : "=r"(q0), "=r"(q1), "=r"(q2), "=r"(q3) : "r"(ad));
            }
            {
                int off = brow1 * 128 + kb + chalf;
                unsigned ad = base + (off ^ ((brow1 & 7) << 4));
                asm volatile("ldmatrix.sync.aligned.m8n8.x4.shared.b16 "
                             "{%0,%1,%2,%3}, [%4];"
                             : "=r"(p0), "=r"(p1), "=r"(p2), "=r"(p3) : "r"(ad));
            }
            // n-blocks: 0 -> {q0,q2}, 1 -> {q1,q3}, 2 -> {p0,p2}, 3 -> {p1,p3}
            #define MMA(J, B0, B1)                                              \
                asm volatile("mma.sync.aligned.m16n8k16.row.col.f32.bf16.bf16.f32 " \
                             "{%0,%1,%2,%3}, {%4,%5,%6,%7}, {%8,%9}, {%0,%1,%2,%3};" \
                             : "+f"(acc[J][0]), "+f"(acc[J][1]),                \
                               "+f"(acc[J][2]), "+f"(acc[J][3])                 \
                             : "r"(a0), "r"(a1), "r"(a2), "r"(a3),              \
                               "r"(B0), "r"(B1))
            MMA(0, q0, q2);
            MMA(1, q1, q3);
            MMA(2, p0, p2);
            MMA(3, p1, p3);
            #undef MMA
        }
        __syncthreads();
    }

    // epilogue: write channel 2 + minmax
    float* o2 = out + ((size_t)(b * 3 + 2)) * 4096;
    const int r0 = wm * 16 + (lane >> 2);
    const int c0 = wn * 32 + (lane & 3) * 2;
    float mn = 3.0e38f, mx = -3.0e38f;
    #pragma unroll
    for (int j = 0; j < 4; ++j) {
        int cc = c0 + j * 8;
        float2 lo = make_float2(acc[j][0], acc[j][1]);
        float2 hi = make_float2(acc[j][2], acc[j][3]);
        *(float2*)(o2 + r0 * 64 + cc) = lo;
        *(float2*)(o2 + (r0 + 8) * 64 + cc) = hi;
        mn = fminf(mn, fminf(fminf(lo.x, lo.y), fminf(hi.x, hi.y)));
        mx = fmaxf(mx, fmaxf(fmaxf(lo.x, lo.y), fmaxf(hi.x, hi.y)));
    }
    block_minmax_atomic(mn, mx, 2);
}

// ---------------------------------------------------------------------------
// Views: one CTA per batch. colmean reduction + both bilinear views in smem.
// Tap math is exact in fp32 (scale denominators are powers of two).
// ---------------------------------------------------------------------------
__global__ void __launch_bounds__(256) k_views(float* __restrict__ out) {
    const int b = blockIdx.x;
    const int t = threadIdx.x;

    __shared__ __align__(16) float srow[EE];
    __shared__ __align__(16) float scol[NN];
    __shared__ int   i0t[2][64], i1t[2][64];
    __shared__ float wt[2][64];

    // row means
    srow[t]       = g_rowmean[b * EE + t];
    srow[t + 256] = g_rowmean[b * EE + t + 256];

    // column means: reduce 32 partials
    {
        float4 s0 = make_float4(0.f, 0.f, 0.f, 0.f);
        float4 s1 = make_float4(0.f, 0.f, 0.f, 0.f);
        const float4* cp = (const float4*)g_colpart + (size_t)b * 32 * (NN / 4);
        #pragma unroll 8
        for (int c = 0; c < 32; ++c) {
            float4 v0 = cp[c * (NN / 4) + t];
            float4 v1 = cp[c * (NN / 4) + t + 256];
            s0.x += v0.x; s0.y += v0.y; s0.z += v0.z; s0.w += v0.w;
            s1.x += v1.x; s1.y += v1.y; s1.z += v1.z; s1.w += v1.w;
        }
        const float k = 1.0f / EE;
        s0.x *= k; s0.y *= k; s0.z *= k; s0.w *= k;
        s1.x *= k; s1.y *= k; s1.z *= k; s1.w *= k;
        ((float4*)scol)[t] = s0;
        ((float4*)scol)[t + 256] = s1;
    }

    // tap tables: sel 0 -> gs=23, sel 1 -> gs=46
    if (t < 128) {
        int sel = t >> 6, o = t & 63;
        int gs = sel ? 46 : 23;
        float src = ((float)o + 0.5f) * ((float)gs / (float)IMGS) - 0.5f;
        src = fminf(fmaxf(src, 0.f), (float)(gs - 1));
        int p0 = (int)floorf(src);
        i0t[sel][o] = p0;
        i1t[sel][o] = min(p0 + 1, gs - 1);
        wt[sel][o]  = src - (float)p0;
    }
    __syncthreads();

    #pragma unroll
    for (int sel = 0; sel < 2; ++sel) {
        const float* v = sel ? scol : srow;
        const int L = sel ? NN : EE;
        const int gs = sel ? 46 : 23;
        float mn = 3.0e38f, mx = -3.0e38f;
        #pragma unroll
        for (int u = 0; u < 16; ++u) {
            int ij = t + 256 * u;
            int i = ij >> 6, j = ij & 63;
            int i0 = i0t[sel][i], i1 = i1t[sel][i];
            int j0 = i0t[sel][j], j1 = i1t[sel][j];
            float wi = wt[sel][i], wj = wt[sel][j];
            int p00 = i0 * gs + j0, p01 = i0 * gs + j1;
            int p10 = i1 * gs + j0, p11 = i1 * gs + j1;
            float v00 = (p00 < L) ? v[p00] : 0.f;
            float v01 = (p01 < L) ? v[p01] : 0.f;
            float v10 = (p10 < L) ? v[p10] : 0.f;
            float v11 = (p11 < L) ? v[p11] : 0.f;
            float val = (1.f - wi) * ((1.f - wj) * v00 + wj * v01) +
                        wi * ((1.f - wj) * v10 + wj * v11);
            out[((size_t)(b * 3 + sel)) * 4096 + ij] = val;
            mn = fminf(mn, val); mx = fmaxf(mx, val);
        }
        block_minmax_atomic(mn, mx, sel);
    }
}

// global per-channel min-max normalization, in place
__global__ void __launch_bounds__(256) k_norm(float* __restrict__ out) {
    int idx = blockIdx.x * blockDim.x + threadIdx.x;  // < B*3*4096
    int ch = (idx >> 12) % 3;
    float lo = fdec(g_mm[2 * ch]);
    float hi = fdec(g_mm[2 * ch + 1]);
    float d = hi - lo;
    float x = out[idx];
    out[idx] = (d < EPSF) ? 0.f : (x - lo) / (d + EPSF);
}

extern "C" void kernel_launch(void* const* d_in, const int* in_sizes, int n_in,
                              void* d_out, int out_size) {
    const float* x = (const float*)d_in[0];
    float* out = (float*)d_out;

    k_pass1<<<dim3(32, 64), 256>>>(x);
    k_gemm<<<64, 256>>>(out);
    k_views<<<64, 256>>>(out);
    k_norm<<<(BB * 3 * 4096) / 256, 256>>>(out);
}

// round 5
// speedup vs baseline: 1.7216x; 1.1926x over previous
#include <cuda_runtime.h>
#include <cuda_bf16.h>
#include <math.h>

#define BB   64
#define EE   512
#define NN   2048
#define IMGS 64
#define EPSF 1e-8f

// ---- scratch (static device globals; no allocation) ----
__device__ __nv_bfloat16 g_y[BB * IMGS * NN];   // 16 MiB  [b][o][n]
__device__ float g_colpart[BB * 32 * NN];       // 16 MiB  [b][chunk][n]
__device__ float g_rowmean[BB * EE];            // 128 KiB
__device__ unsigned g_mm[6];                    // min/max per channel (encoded)

// order-preserving float<->uint encoding for atomic min/max
__device__ __forceinline__ unsigned fenc(float f) {
    unsigned u = __float_as_uint(f);
    return (u & 0x80000000u) ? ~u : (u | 0x80000000u);
}
__device__ __forceinline__ float fdec(unsigned e) {
    unsigned u = (e & 0x80000000u) ? (e ^ 0x80000000u) : ~e;
    return __uint_as_float(u);
}

__device__ __forceinline__ unsigned smem_u32(const void* p) {
    unsigned a;
    asm("{ .reg .u64 t; cvta.to.shared.u64 t, %1; cvt.u32.u64 %0, t; }"
        : "=r"(a) : "l"(p));
    return a;
}

// block-wide minmax -> global atomics (entry sync so it can be called twice)
__device__ __forceinline__ void block_minmax_atomic(float mn, float mx, int ch) {
    __shared__ float smn[8], smx[8];
    __syncthreads();
    #pragma unroll
    for (int o = 16; o; o >>= 1) {
        mn = fminf(mn, __shfl_down_sync(0xFFFFFFFFu, mn, o));
        mx = fmaxf(mx, __shfl_down_sync(0xFFFFFFFFu, mx, o));
    }
    int lane = threadIdx.x & 31, warp = threadIdx.x >> 5;
    if (lane == 0) { smn[warp] = mn; smx[warp] = mx; }
    __syncthreads();
    if (threadIdx.x == 0) {
        float a = smn[0], c = smx[0];
        #pragma unroll
        for (int w = 1; w < 8; ++w) { a = fminf(a, smn[w]); c = fmaxf(c, smx[w]); }
        atomicMin(&g_mm[2 * ch], fenc(a));
        atomicMax(&g_mm[2 * ch + 1], fenc(c));
    }
}

// ---------------------------------------------------------------------------
// Pass 1: one CTA per (batch, 16-row chunk). Streams input once.
//  - per-row mean -> g_rowmean (temporal raw)
//  - rows chunk*16+{3,4} -> y row 2*chunk ; +{11,12} -> y row 2*chunk+1
//    (centered, normalized, 0.5 resize weight folded; stored bf16)
//  - partial column sums over the 16 rows -> g_colpart
// ---------------------------------------------------------------------------
__global__ void __launch_bounds__(256) k_pass1(const float* __restrict__ x) {
    const int chunk = blockIdx.x;   // 0..31
    const int b     = blockIdx.y;   // 0..63
    const int t     = threadIdx.x;  // 0..255
    const int lane  = t & 31, warp = t >> 5;

    if (chunk == 0 && b == 0) {     // fold g_mm init in (consumers run later)
        if (t < 3) g_mm[2 * t] = 0xFFFFFFFFu;
        else if (t < 6) g_mm[2 * (t - 3) + 1] = 0u;
    }

    __shared__ float4 rows[4][512];          // rows 3,4,11,12 of the chunk
    __shared__ float wsum[8][16], wsq[8][4];
    __shared__ float rsum[16], rsq[4];

    float4 cs0 = make_float4(0.f, 0.f, 0.f, 0.f);
    float4 cs1 = make_float4(0.f, 0.f, 0.f, 0.f);
    float ps[16], pq[4];

    const float4* base = (const float4*)x + ((size_t)(b * EE + chunk * 16) * NN) / 4;

    #pragma unroll
    for (int r = 0; r < 16; ++r) {
        const float4* rp = base + (size_t)r * (NN / 4);
        float4 v0 = rp[t];
        float4 v1 = rp[t + 256];

        cs0.x += v0.x; cs0.y += v0.y; cs0.z += v0.z; cs0.w += v0.w;
        cs1.x += v1.x; cs1.y += v1.y; cs1.z += v1.z; cs1.w += v1.w;

        ps[r] = v0.x + v0.y + v0.z + v0.w + v1.x + v1.y + v1.z + v1.w;

        // sumsq + row stash only for the 4 selected rows
        int si = -1;
        if (r == 3)  si = 0;
        if (r == 4)  si = 1;
        if (r == 11) si = 2;
        if (r == 12) si = 3;
        if (si >= 0) {
            rows[si][t] = v0; rows[si][t + 256] = v1;
            pq[si] = v0.x * v0.x + v0.y * v0.y + v0.z * v0.z + v0.w * v0.w +
                     v1.x * v1.x + v1.y * v1.y + v1.z * v1.z + v1.w * v1.w;
        }
    }

    #pragma unroll
    for (int r = 0; r < 16; ++r) {
        float s = ps[r];
        #pragma unroll
        for (int o = 16; o; o >>= 1)
            s += __shfl_down_sync(0xFFFFFFFFu, s, o);
        if (lane == 0) wsum[warp][r] = s;
    }
    #pragma unroll
    for (int p = 0; p < 4; ++p) {
        float q = pq[p];
        #pragma unroll
        for (int o = 16; o; o >>= 1)
            q += __shfl_down_sync(0xFFFFFFFFu, q, o);
        if (lane == 0) wsq[warp][p] = q;
    }
    __syncthreads();
    if (t < 16) {
        float S = 0.f;
        #pragma unroll
        for (int w = 0; w < 8; ++w) S += wsum[w][t];
        rsum[t] = S;
        g_rowmean[b * EE + chunk * 16 + t] = S * (1.0f / NN);
    }
    if (t >= 32 && t < 36) {
        int p = t - 32;
        float Q = 0.f;
        #pragma unroll
        for (int w = 0; w < 8; ++w) Q += wsq[w][p];
        rsq[p] = Q;
    }
    __syncthreads();

    // stats of the four selected rows; fold 0.5 resize weight into inv-norm
    float m[4], inv[4];
    const int sel[4] = {3, 4, 11, 12};
    #pragma unroll
    for (int p = 0; p < 4; ++p) {
        m[p] = rsum[sel[p]] * (1.0f / NN);
        float q = fmaxf(rsq[p] - (float)NN * m[p] * m[p], 0.f);
        inv[p] = 0.5f / (sqrtf(q) + EPSF);
    }

    #pragma unroll
    for (int half = 0; half < 2; ++half) {  // half 0 -> y row 2c, 1 -> 2c+1
        uint2* yb = (uint2*)(g_y + (size_t)(b * IMGS + chunk * 2 + half) * NN);
        const float mA = m[2 * half], mB = m[2 * half + 1];
        const float iA = inv[2 * half], iB = inv[2 * half + 1];
        #pragma unroll
        for (int u = 0; u < 2; ++u) {
            float4 a = rows[2 * half][t + 256 * u];
            float4 c = rows[2 * half + 1][t + 256 * u];
            float4 y;
            y.x = (a.x - mA) * iA + (c.x - mB) * iB;
            y.y = (a.y - mA) * iA + (c.y - mB) * iB;
            y.z = (a.z - mA) * iA + (c.z - mB) * iB;
            y.w = (a.w - mA) * iA + (c.w - mB) * iB;
            __nv_bfloat162 h0 = __floats2bfloat162_rn(y.x, y.y);
            __nv_bfloat162 h1 = __floats2bfloat162_rn(y.z, y.w);
            uint2 pk;
            pk.x = *(unsigned*)&h0;
            pk.y = *(unsigned*)&h1;
            yb[t + 256 * u] = pk;
        }
    }

    float4* cp = (float4*)g_colpart + ((size_t)(b * 32 + chunk) * NN) / 4;
    cp[t] = cs0; cp[t + 256] = cs1;
}

// ---------------------------------------------------------------------------
// Fused middle kernel, grid = 192:
//  blocks 0..127  : corr GEMM (2 CTAs per batch: row halves), bf16 mma.sync
//  blocks 128..191: temporal+spatial bilinear views (1 CTA per batch)
// ---------------------------------------------------------------------------
__global__ void __launch_bounds__(256) k_fused(float* __restrict__ out) {
    __shared__ __align__(16) char smraw[16384];  // union: gemm tiles / view arrays
    const int t = threadIdx.x;

    if (blockIdx.x < 128) {
        // ================= GEMM branch =================
        const int b = blockIdx.x >> 1;
        const int s = blockIdx.x & 1;            // row half: rows s*32..s*32+31
        const int warp = t >> 5, lane = t & 31;
        const int wm = warp >> 2;                // 0..1 -> +16 rows
        const int wn = warp & 3;                 // 0..3 -> 16*wn cols

        char (*sm)[64 * 128] = (char (*)[64 * 128])smraw;  // [2][8192] dbuf
        const __nv_bfloat16* Yb = g_y + (size_t)b * IMGS * NN;

        const int lrow = t >> 2;                 // loader row 0..63
        const int lch0 = (t & 3) * 2;            // two 16B chunks

        const int arow = s * 32 + wm * 16 + (lane & 15);
        const int brow = wn * 16 + (lane & 15);
        const int chalf = (lane >> 4) * 16;
        const unsigned smb = smem_u32(smraw);

        float acc[2][4];
        #pragma unroll
        for (int j = 0; j < 2; ++j)
            #pragma unroll
            for (int r = 0; r < 4; ++r) acc[j][r] = 0.f;

        {   // preload tile 0
            const uint4* src = (const uint4*)(Yb + (size_t)lrow * NN);
            #pragma unroll
            for (int u = 0; u < 2; ++u) {
                int ch = lch0 + u;
                uint4 v = src[ch];
                int off = lrow * 128 + ch * 16;
                *(uint4*)(smraw + (off ^ ((lrow & 7) << 4))) = v;
            }
        }
        __syncthreads();

        for (int kt = 0; kt < 32; ++kt) {
            const int buf = kt & 1;
            if (kt + 1 < 32) {
                const uint4* src = (const uint4*)(Yb + (size_t)lrow * NN + (kt + 1) * 64);
                #pragma unroll
                for (int u = 0; u < 2; ++u) {
                    int ch = lch0 + u;
                    uint4 v = src[ch];
                    int off = lrow * 128 + ch * 16;
                    *(uint4*)(sm[buf ^ 1] + (off ^ ((lrow & 7) << 4))) = v;
                }
            }

            const unsigned base = smb + buf * (64 * 128);
            #pragma unroll
            for (int ks = 0; ks < 4; ++ks) {
                const int kb = ks * 32;
                unsigned a0, a1, a2, a3, b0, b1, b2, b3;
                {
                    int off = arow * 128 + kb + chalf;
                    unsigned ad = base + (off ^ ((arow & 7) << 4));
                    asm volatile("ldmatrix.sync.aligned.m8n8.x4.shared.b16 "
                                 "{%0,%1,%2,%3}, [%4];"
                                 : "=r"(a0), "=r"(a1), "=r"(a2), "=r"(a3) : "r"(ad));
                }
                {
                    int off = brow * 128 + kb + chalf;
                    unsigned ad = base + (off ^ ((brow & 7) << 4));
                    asm volatile("ldmatrix.sync.aligned.m8n8.x4.shared.b16 "
                                 "{%0,%1,%2,%3}, [%4];"
                                 : "=r"(b0), "=r"(b1), "=r"(b2), "=r"(b3) : "r"(ad));
                }
                #define MMA(J, B0, B1)                                              \
                    asm volatile("mma.sync.aligned.m16n8k16.row.col.f32.bf16.bf16.f32 " \
                                 "{%0,%1,%2,%3}, {%4,%5,%6,%7}, {%8,%9}, {%0,%1,%2,%3};" \
                                 : "+f"(acc[J][0]), "+f"(acc[J][1]),                \
                                   "+f"(acc[J][2]), "+f"(acc[J][3])                 \
                                 : "r"(a0), "r"(a1), "r"(a2), "r"(a3),              \
                                   "r"(B0), "r"(B1))
                MMA(0, b0, b2);
                MMA(1, b1, b3);
                #undef MMA
            }
            __syncthreads();
        }

        float* o2 = out + ((size_t)(b * 3 + 2)) * 4096;
        const int r0 = s * 32 + wm * 16 + (lane >> 2);
        const int c0 = wn * 16 + (lane & 3) * 2;
        float mn = 3.0e38f, mx = -3.0e38f;
        #pragma unroll
        for (int j = 0; j < 2; ++j) {
            int cc = c0 + j * 8;
            float2 lo = make_float2(acc[j][0], acc[j][1]);
            float2 hi = make_float2(acc[j][2], acc[j][3]);
            *(float2*)(o2 + r0 * 64 + cc) = lo;
            *(float2*)(o2 + (r0 + 8) * 64 + cc) = hi;
            mn = fminf(mn, fminf(fminf(lo.x, lo.y), fminf(hi.x, hi.y)));
            mx = fmaxf(mx, fmaxf(fmaxf(lo.x, lo.y), fmaxf(hi.x, hi.y)));
        }
        block_minmax_atomic(mn, mx, 2);
    } else {
        // ================= views branch =================
        const int b = blockIdx.x - 128;

        float* srow = (float*)smraw;                    // 512 f  @0
        float* scol = (float*)(smraw + 2048);           // 2048 f @2048
        int*   i0t  = (int*)(smraw + 10240);            // [2][64]
        int*   i1t  = (int*)(smraw + 10752);            // [2][64]
        float* wt   = (float*)(smraw + 11264);          // [2][64]

        srow[t]       = g_rowmean[b * EE + t];
        srow[t + 256] = g_rowmean[b * EE + t + 256];

        {   // column means: reduce 32 partials
            float4 s0 = make_float4(0.f, 0.f, 0.f, 0.f);
            float4 s1 = make_float4(0.f, 0.f, 0.f, 0.f);
            const float4* cp = (const float4*)g_colpart + (size_t)b * 32 * (NN / 4);
            #pragma unroll 8
            for (int c = 0; c < 32; ++c) {
                float4 v0 = cp[c * (NN / 4) + t];
                float4 v1 = cp[c * (NN / 4) + t + 256];
                s0.x += v0.x; s0.y += v0.y; s0.z += v0.z; s0.w += v0.w;
                s1.x += v1.x; s1.y += v1.y; s1.z += v1.z; s1.w += v1.w;
            }
            const float k = 1.0f / EE;
            s0.x *= k; s0.y *= k; s0.z *= k; s0.w *= k;
            s1.x *= k; s1.y *= k; s1.z *= k; s1.w *= k;
            ((float4*)scol)[t] = s0;
            ((float4*)scol)[t + 256] = s1;
        }

        if (t < 128) {  // tap tables (fp32-exact: denominators are powers of 2)
            int sel = t >> 6, o = t & 63;
            int gs = sel ? 46 : 23;
            float src = ((float)o + 0.5f) * ((float)gs / (float)IMGS) - 0.5f;
            src = fminf(fmaxf(src, 0.f), (float)(gs - 1));
            int p0 = (int)floorf(src);
            i0t[sel * 64 + o] = p0;
            i1t[sel * 64 + o] = min(p0 + 1, gs - 1);
            wt[sel * 64 + o]  = src - (float)p0;
        }
        __syncthreads();

        #pragma unroll
        for (int sel = 0; sel < 2; ++sel) {
            const float* v = sel ? scol : srow;
            const int L = sel ? NN : EE;
            const int gs = sel ? 46 : 23;
            float mn = 3.0e38f, mx = -3.0e38f;
            #pragma unroll
            for (int u = 0; u < 16; ++u) {
                int ij = t + 256 * u;
                int i = ij >> 6, j = ij & 63;
                int i0 = i0t[sel * 64 + i], i1 = i1t[sel * 64 + i];
                int j0 = i0t[sel * 64 + j], j1 = i1t[sel * 64 + j];
                float wi = wt[sel * 64 + i], wj = wt[sel * 64 + j];
                int p00 = i0 * gs + j0, p01 = i0 * gs + j1;
                int p10 = i1 * gs + j0, p11 = i1 * gs + j1;
                float v00 = (p00 < L) ? v[p00] : 0.f;
                float v01 = (p01 < L) ? v[p01] : 0.f;
                float v10 = (p10 < L) ? v[p10] : 0.f;
                float v11 = (p11 < L) ? v[p11] : 0.f;
                float val = (1.f - wi) * ((1.f - wj) * v00 + wj * v01) +
                            wi * ((1.f - wj) * v10 + wj * v11);
                out[((size_t)(b * 3 + sel)) * 4096 + ij] = val;
                mn = fminf(mn, val); mx = fmaxf(mx, val);
            }
            block_minmax_atomic(mn, mx, sel);
        }
    }
}

// global per-channel min-max normalization, in place (float4 grid-stride)
__global__ void __launch_bounds__(256) k_norm(float* __restrict__ out) {
    float4* o4 = (float4*)out;
    const int n4 = BB * 3 * 4096 / 4;              // 196608
    float lo[3], inv[3];
    #pragma unroll
    for (int c = 0; c < 3; ++c) {
        float l = fdec(g_mm[2 * c]);
        float h = fdec(g_mm[2 * c + 1]);
        float d = h - l;
        lo[c] = l;
        inv[c] = (d < EPSF) ? 0.f : 1.0f / (d + EPSF);
    }
    for (int i = blockIdx.x * blockDim.x + threadIdx.x; i < n4;
         i += gridDim.x * blockDim.x) {
        int ch = (i >> 10) % 3;                    // 4096 floats = 1024 float4 per ch
        float4 v = o4[i];
        v.x = (v.x - lo[ch]) * inv[ch];
        v.y = (v.y - lo[ch]) * inv[ch];
        v.z = (v.z - lo[ch]) * inv[ch];
        v.w = (v.w - lo[ch]) * inv[ch];
        o4[i] = v;
    }
}

extern "C" void kernel_launch(void* const* d_in, const int* in_sizes, int n_in,
                              void* d_out, int out_size) {
    const float* x = (const float*)d_in[0];
    float* out = (float*)d_out;

    k_pass1<<<dim3(32, 64), 256>>>(x);
    k_fused<<<192, 256>>>(out);
    k_norm<<<192, 256>>>(out);
}